// round 5
// baseline (speedup 1.0000x reference)
#include <cuda_runtime.h>
#include <cuda_bf16.h>
#include <math.h>
#include <stdint.h>

// ---------------- constants / scratch ----------------
#define MAXB    8192
#define MAXC    8
#define DDIM    512
#define KA      1024          // A rows: [hi | lo]
#define KB      512           // B rows: [hi]  (chunks 8..15 reuse chunks 0..7)
// log2(e)/TEMP, TEMP=0.07
#define CEXP    20.60992915555662f
// np.finfo(float32).eps
#define EPSF    1.1920928955078125e-07f

// GEMM tiling: block 128x256, 8 warps (2M x 4N), warp tile 64x64
#define TM      128
#define TN      256
#define KC      64            // bf16 per K-chunk (128 bytes per row)
#define NCHUNK  (KA / KC)     // 16
#define NSTAGE  3
#define A_BYTES (TM * 128)    // 16384
#define B_BYTES (TN * 128)    // 32768
#define STAGE_BYTES (A_BYTES + B_BYTES)       // 49152
#define SMEM_TOTAL  (NSTAGE * STAGE_BYTES)    // 147456

__device__ int   g_posIdx[MAXB];
__device__ int   g_negIdx[MAXB];
__device__ int   g_counts[1];
__device__ float g_diag[MAXB];
__device__ float g_diagP[MAXB];
__device__ float g_S1i[MAXB], g_S2i[MAXB], g_S1t[MAXB], g_S2t[MAXB];
__device__ float g_ce_sum[MAXC], g_last_sum[MAXC];
__device__ int   g_cnt[MAXC];
__device__ int   g_winI[1048576], g_winT[1048576];
__device__ float g_sIv[MAXB], g_sTv[MAXB];
__device__ int   g_iid[MAXB], g_tid2[MAXB];

// bf16-split gathered matrices
__device__ __align__(16) __nv_bfloat16 g_imgP[(size_t)MAXB * KA];
__device__ __align__(16) __nv_bfloat16 g_txtP[(size_t)MAXB * KA];
__device__ __align__(16) __nv_bfloat16 g_imgN[(size_t)MAXB * KB];
__device__ __align__(16) __nv_bfloat16 g_txtN[(size_t)MAXB * KB];

// ---------------- PTX helpers (baseline ISA only: sm_80+) ----------------
__device__ __forceinline__ uint32_t smem_to_u32(const void* p) {
    uint32_t a;
    asm("{ .reg .u64 t; cvta.to.shared.u64 t, %1; cvt.u32.u64 %0, t; }" : "=r"(a) : "l"(p));
    return a;
}
#define CP_ASYNC16(sm, g) \
    asm volatile("cp.async.cg.shared.global [%0], [%1], 16;" :: "r"(sm), "l"(g))
#define CP_COMMIT() asm volatile("cp.async.commit_group;" ::: "memory")
#define CP_WAIT1()  asm volatile("cp.async.wait_group 1;"  ::: "memory")

__device__ __forceinline__ void ldsm_x4(uint32_t& r0, uint32_t& r1, uint32_t& r2,
                                        uint32_t& r3, uint32_t addr) {
    asm volatile("ldmatrix.sync.aligned.m8n8.x4.shared.b16 {%0,%1,%2,%3}, [%4];"
                 : "=r"(r0), "=r"(r1), "=r"(r2), "=r"(r3) : "r"(addr));
}
__device__ __forceinline__ void mma16816(float& c0, float& c1, float& c2, float& c3,
                                         uint32_t a0, uint32_t a1, uint32_t a2, uint32_t a3,
                                         uint32_t b0, uint32_t b1) {
    asm volatile(
        "mma.sync.aligned.m16n8k16.row.col.f32.bf16.bf16.f32 "
        "{%0,%1,%2,%3}, {%4,%5,%6,%7}, {%8,%9}, {%0,%1,%2,%3};"
        : "+f"(c0), "+f"(c1), "+f"(c2), "+f"(c3)
        : "r"(a0), "r"(a1), "r"(a2), "r"(a3), "r"(b0), "r"(b1));
}
__device__ __forceinline__ uint32_t sw128(uint32_t off) { return off ^ ((off >> 3) & 0x70); }

// ---------------- stable pos/neg compaction (1 block) ----------------
__global__ void compact_kernel(const int* __restrict__ slabel, int B) {
    __shared__ int scan[1024];
    int t   = threadIdx.x;
    int ipt = (B + 1023) >> 10;
    int base = t * ipt;
    int cnt = 0;
    for (int i = 0; i < ipt; i++) {
        int gi = base + i;
        if (gi < B && slabel[gi] == 1) cnt++;
    }
    scan[t] = cnt;
    __syncthreads();
    for (int off = 1; off < 1024; off <<= 1) {
        int v = (t >= off) ? scan[t - off] : 0;
        __syncthreads();
        scan[t] += v;
        __syncthreads();
    }
    int pr = scan[t] - cnt;
    for (int i = 0; i < ipt; i++) {
        int gi = base + i;
        if (gi >= B) break;
        if (slabel[gi] == 1) { g_posIdx[pr] = gi; pr++; }
        else                 { g_negIdx[gi - pr] = gi; }
    }
    if (t == 1023) g_counts[0] = scan[1023];
}

// ---------------- diag[i] = img[i] . txt[i] ----------------
__global__ void diag_kernel(const float* __restrict__ img,
                            const float* __restrict__ txt, int D, int B) {
    int gw   = (blockIdx.x * blockDim.x + threadIdx.x) >> 5;
    int lane = threadIdx.x & 31;
    if (gw >= B) return;
    const float4* a = (const float4*)(img + (size_t)gw * D);
    const float4* b = (const float4*)(txt + (size_t)gw * D);
    float s = 0.f;
    int n4 = D >> 2;
    for (int k = lane; k < n4; k += 32) {
        float4 x = a[k], y = b[k];
        s += x.x * y.x + x.y * y.y + x.z * y.z + x.w * y.w;
    }
    #pragma unroll
    for (int o = 16; o > 0; o >>= 1) s += __shfl_down_sync(0xffffffffu, s, o);
    if (lane == 0) g_diag[gw] = s;
}

// ---------------- copy persistent buffers into out + zero accumulators ----------------
__global__ void prep_kernel(float* __restrict__ dst, const float* __restrict__ sI,
                            const float* __restrict__ sT, int N) {
    int id  = blockIdx.x * blockDim.x + threadIdx.x;
    int str = gridDim.x * blockDim.x;
    // zero accumulators (small)
    for (int i = id; i < MAXB; i += str) {
        g_S1i[i] = 0.f; g_S2i[i] = 0.f; g_S1t[i] = 0.f; g_S2t[i] = 0.f;
    }
    if (id < MAXC) { g_ce_sum[id] = 0.f; g_last_sum[id] = 0.f; g_cnt[id] = 0; }
    // vectorized copy: dst[i] = (i<N)? sI[i] : sT[i-N], dst is unaligned (+1 float)
    int tot4 = (2 * N) >> 2;
    for (int i = id; i < tot4; i += str) {
        int base = i * 4;
        float4 v;
        if (base + 3 < N) {
            v = *(const float4*)(sI + base);
        } else if (base >= N) {
            v = *(const float4*)(sT + (base - N));
        } else {
            v.x = (base     < N) ? sI[base]     : sT[base - N];
            v.y = (base + 1 < N) ? sI[base + 1] : sT[base + 1 - N];
            v.z = (base + 2 < N) ? sI[base + 2] : sT[base + 2 - N];
            v.w = (base + 3 < N) ? sI[base + 3] : sT[base + 3 - N];
        }
        dst[base] = v.x; dst[base + 1] = v.y; dst[base + 2] = v.z; dst[base + 3] = v.w;
    }
    for (int i = tot4 * 4 + id; i < 2 * N; i += str)
        dst[i] = (i < N) ? sI[i] : sT[i - N];
}

// ---------------- gather + bf16 split/convert ----------------
// pos rows (A operands, stride KA): [hi | lo]; neg rows (B operands, stride KB): [hi]
__global__ void gather_kernel(const float* __restrict__ img,
                              const float* __restrict__ txt, int B) {
    int P = g_counts[0];
    int s = blockIdx.x;
    if (s >= B) return;
    int t = threadIdx.x;          // 256 threads, 2 elems each
    bool isPos = (s < P);
    int src;
    __nv_bfloat16 *dI, *dT;
    if (isPos) {
        src = g_posIdx[s];
        dI = g_imgP + (size_t)s * KA; dT = g_txtP + (size_t)s * KA;
        if (t == 0) g_diagP[s] = g_diag[src];
    } else {
        int n = s - P;
        src = g_negIdx[n];
        dI = g_imgN + (size_t)n * KB; dT = g_txtN + (size_t)n * KB;
    }
    int k2 = 2 * t;               // D = 512, 256 threads
    {
        float2 v = *(const float2*)(img + (size_t)src * DDIM + k2);
        __nv_bfloat16 h0 = __float2bfloat16_rn(v.x);
        __nv_bfloat16 h1 = __float2bfloat16_rn(v.y);
        __nv_bfloat162 hh; hh.x = h0; hh.y = h1;
        *(__nv_bfloat162*)(dI + k2) = hh;
        if (isPos) {
            __nv_bfloat162 ll;
            ll.x = __float2bfloat16_rn(v.x - __bfloat162float(h0));
            ll.y = __float2bfloat16_rn(v.y - __bfloat162float(h1));
            *(__nv_bfloat162*)(dI + DDIM + k2) = ll;
        }
    }
    {
        float2 v = *(const float2*)(txt + (size_t)src * DDIM + k2);
        __nv_bfloat16 h0 = __float2bfloat16_rn(v.x);
        __nv_bfloat16 h1 = __float2bfloat16_rn(v.y);
        __nv_bfloat162 hh; hh.x = h0; hh.y = h1;
        *(__nv_bfloat162*)(dT + k2) = hh;
        if (isPos) {
            __nv_bfloat162 ll;
            ll.x = __float2bfloat16_rn(v.x - __bfloat162float(h0));
            ll.y = __float2bfloat16_rn(v.y - __bfloat162float(h1));
            *(__nv_bfloat162*)(dT + DDIM + k2) = ll;
        }
    }
}

// ---------------- mma.sync bf16 GEMM + fused exp epilogue ----------------
// z==0: A=g_imgP, B=g_txtN -> S1i/S2i ; z==1: A=g_txtP, B=g_imgN -> S1t/S2t
// Block 128x256, 8 warps (2M x 4N), warp tile 64x64, 3-stage cp.async pipeline.
__global__ void __launch_bounds__(256, 1)
mma_gemm(int Btot) {
    int M     = g_counts[0];
    int Ncols = Btot - M;
    int br = blockIdx.y * TM;
    int bc = blockIdx.x * TN;
    if (br >= M || bc >= Ncols) return;
    int which = blockIdx.z;

    extern __shared__ char smem[];
    uint32_t smem_base = smem_to_u32(smem);
    int tid  = threadIdx.x;
    int wid  = tid >> 5;
    int lane = tid & 31;
    int warp_m = wid >> 2;    // 0..1
    int warp_n = wid & 3;     // 0..3

    const __nv_bfloat16* Abuf = which ? g_txtP : g_imgP;
    const __nv_bfloat16* Bbuf = which ? g_imgN : g_txtN;

    // cp.async plan: unit u = tid + j*256: row = u>>3 = (tid>>3)+32j, kb = (u&7)*16
    // A: j=0..3 (128 rows), B: j=0..7 (256 rows). Swizzle is j-invariant: +4096B per j.
    int ldRow = tid >> 3;
    int ldKb  = (tid & 7) * 16;
    const char* gA0 = (const char*)Abuf + ((size_t)(br + ldRow) * KA) * 2 + ldKb;
    const char* gB0 = (const char*)Bbuf + ((size_t)(bc + ldRow) * KB) * 2 + ldKb;
    uint32_t ldOff = sw128((uint32_t)ldRow * 128 + (uint32_t)ldKb);
    const size_t rowStrA = (size_t)32 * KA * 2;
    const size_t rowStrB = (size_t)32 * KB * 2;

    // ldmatrix address components
    uint32_t aRow = (uint32_t)(warp_m * 64 + (lane & 15));
    uint32_t aKb  = (uint32_t)((lane >> 4) * 16);
    uint32_t bRow = (uint32_t)(warp_n * 64 + (lane & 7) + ((lane >> 4) << 3));
    uint32_t bKb  = (uint32_t)(((lane >> 3) & 1) * 16);

    float acc[4][8][4];
    #pragma unroll
    for (int i = 0; i < 4; i++)
        #pragma unroll
        for (int j = 0; j < 8; j++)
            #pragma unroll
            for (int q = 0; q < 4; q++) acc[i][j][q] = 0.f;

    // prefetch chunks 0,1 (stages 0,1)
    #pragma unroll
    for (int pc = 0; pc < 2; pc++) {
        uint32_t sA = smem_base + pc * STAGE_BYTES;
        uint32_t sB = sA + A_BYTES;
        const char* pA = gA0 + (size_t)pc * 128;
        const char* pB = gB0 + (size_t)pc * 128;
        #pragma unroll
        for (int j = 0; j < 4; j++)
            CP_ASYNC16(sA + ldOff + j * 4096, pA + j * rowStrA);
        #pragma unroll
        for (int j = 0; j < 8; j++)
            CP_ASYNC16(sB + ldOff + j * 4096, pB + j * rowStrB);
        CP_COMMIT();
    }

    int stC = 0;   // stage of chunk c
    for (int c = 0; c < NCHUNK; c++) {
        CP_WAIT1();
        __syncthreads();
        // prefetch c+2 into stage (c+2)%3 (safe: all threads past compute of c-1)
        if (c + 2 < NCHUNK) {
            int sp = stC + 2; if (sp >= NSTAGE) sp -= NSTAGE;
            uint32_t sA = smem_base + sp * STAGE_BYTES;
            uint32_t sB = sA + A_BYTES;
            const char* pA = gA0 + (size_t)(c + 2) * 128;
            const char* pB = gB0 + (size_t)((c + 2) & 7) * 128;
            #pragma unroll
            for (int j = 0; j < 4; j++)
                CP_ASYNC16(sA + ldOff + j * 4096, pA + j * rowStrA);
            #pragma unroll
            for (int j = 0; j < 8; j++)
                CP_ASYNC16(sB + ldOff + j * 4096, pB + j * rowStrB);
        }
        CP_COMMIT();

        uint32_t sA = smem_base + stC * STAGE_BYTES;
        uint32_t sB = sA + A_BYTES;
        #pragma unroll
        for (int k16 = 0; k16 < 4; k16++) {
            uint32_t kbase = (uint32_t)(k16 * 32);
            uint32_t a[4][4];
            #pragma unroll
            for (int mt = 0; mt < 4; mt++) {
                uint32_t addr = sA + sw128((aRow + mt * 16) * 128 + kbase + aKb);
                ldsm_x4(a[mt][0], a[mt][1], a[mt][2], a[mt][3], addr);
            }
            uint32_t b[8][2];
            #pragma unroll
            for (int np = 0; np < 4; np++) {
                uint32_t addr = sB + sw128((bRow + np * 16) * 128 + kbase + bKb);
                uint32_t r0, r1, r2, r3;
                ldsm_x4(r0, r1, r2, r3, addr);
                b[np * 2][0] = r0; b[np * 2][1] = r1;
                b[np * 2 + 1][0] = r2; b[np * 2 + 1][1] = r3;
            }
            #pragma unroll
            for (int mt = 0; mt < 4; mt++)
                #pragma unroll
                for (int nt = 0; nt < 8; nt++)
                    mma16816(acc[mt][nt][0], acc[mt][nt][1], acc[mt][nt][2], acc[mt][nt][3],
                             a[mt][0], a[mt][1], a[mt][2], a[mt][3],
                             b[nt][0], b[nt][1]);
        }
        if (++stC >= NSTAGE) stC = 0;
    }

    // fused epilogue: d = acc - diag; e = exp(d/T); S1 += e; S2 += e*d
    float* S1 = which ? g_S1t : g_S1i;
    float* S2 = which ? g_S2t : g_S2i;
    int quad = lane & 3;
    #pragma unroll
    for (int mt = 0; mt < 4; mt++) {
        #pragma unroll
        for (int half = 0; half < 2; half++) {
            int rl = warp_m * 64 + mt * 16 + (lane >> 2) + half * 8;
            int rg = br + rl;
            float dg = (rg < M) ? g_diagP[rg] : 0.f;
            float s1 = 0.f, s2 = 0.f;
            #pragma unroll
            for (int nt = 0; nt < 8; nt++) {
                #pragma unroll
                for (int q = 0; q < 2; q++) {
                    int cg = bc + warp_n * 64 + nt * 8 + quad * 2 + q;
                    if (cg < Ncols) {
                        float d = acc[mt][nt][half * 2 + q] - dg;
                        float e = exp2f(d * CEXP);
                        s1 += e;
                        s2 += e * d;
                    }
                }
            }
            s1 += __shfl_down_sync(0xffffffffu, s1, 1, 4);
            s1 += __shfl_down_sync(0xffffffffu, s1, 2, 4);
            s2 += __shfl_down_sync(0xffffffffu, s2, 1, 4);
            s2 += __shfl_down_sync(0xffffffffu, s2, 2, 4);
            if (quad == 0 && rg < M) {
                atomicAdd(&S1[rg], s1);
                atomicAdd(&S2[rg], s2);
            }
        }
    }
}

// ---------------- CE penalty branch ----------------
__global__ void ce_kernel(const float* __restrict__ imgc, const float* __restrict__ txtc,
                          const int* __restrict__ labels, const float* __restrict__ lastl,
                          int Bc, int D, int C) {
    __shared__ float sw[2560];
    int t = threadIdx.x;
    for (int i = t; i < C * D; i += blockDim.x) sw[i] = txtc[i];
    __syncthreads();

    int gw   = (blockIdx.x * blockDim.x + t) >> 5;
    int lane = t & 31;
    if (gw >= Bc) return;

    const float4* a = (const float4*)(imgc + (size_t)gw * D);
    float acc[5] = {0.f, 0.f, 0.f, 0.f, 0.f};
    int n4 = D >> 2;
    for (int k = lane; k < n4; k += 32) {
        float4 x = a[k];
        #pragma unroll
        for (int c = 0; c < 5; c++) {
            float4 w = *(const float4*)&sw[c * D + k * 4];
            acc[c] += x.x * w.x + x.y * w.y + x.z * w.z + x.w * w.w;
        }
    }
    #pragma unroll
    for (int c = 0; c < 5; c++) {
        #pragma unroll
        for (int o = 16; o > 0; o >>= 1)
            acc[c] += __shfl_down_sync(0xffffffffu, acc[c], o);
    }
    if (lane == 0) {
        float logits[5], m = -1e30f;
        #pragma unroll
        for (int c = 0; c < 5; c++) { logits[c] = acc[c] * 10.0f; m = fmaxf(m, logits[c]); }
        float se = 0.f;
        #pragma unroll
        for (int c = 0; c < 5; c++) se += expf(logits[c] - m);
        float lse = m + logf(se);
        int lb = labels[gw];
        float ce = lse - logits[lb];
        atomicAdd(&g_ce_sum[lb], ce);
        atomicAdd(&g_cnt[lb], 1);
        atomicAdd(&g_last_sum[lb], lastl[gw]);
    }
}

// ---------------- finalize (single block) ----------------
__global__ void finalize_kernel(const int* __restrict__ image_ids,
                                const int* __restrict__ text_ids,
                                const float* __restrict__ s_I,
                                const float* __restrict__ s_T,
                                const float* __restrict__ u_in,
                                const int* __restrict__ epoch_ptr,
                                float* __restrict__ out, int N, int C, int B) {
    __shared__ float redI[1024], redT[1024];
    int t = threadIdx.x;
    int P = g_counts[0];
    int Nn = B - P;
    int epoch = *epoch_ptr;
    float invNn = 1.0f / (float)Nn;
    float* outSI = out + 1;
    float* outST = out + 1 + N;

    float li = 0.f, lt = 0.f;
    for (int p = t; p < P; p += 1024) {
        int row = g_posIdx[p];
        float gI = g_S1i[p] * invNn;
        float gT = g_S1t[p] * invNn;
        int iid = image_ids[row];
        int tid = text_ids[row];
        float sIv, sTv;
        if (epoch == 0) { sIv = gI; sTv = gT; }
        else {
            sIv = 0.2f * s_I[iid] + 0.8f * gI;
            sTv = 0.2f * s_T[tid] + 0.8f * gT;
        }
        li += (g_S2i[p] * invNn) / (sIv + EPSF);
        lt += (g_S2t[p] * invNn) / (sTv + EPSF);
        g_sIv[p] = sIv; g_sTv[p] = sTv;
        g_iid[p] = iid; g_tid2[p] = tid;
        g_winI[iid] = -1;
        g_winT[tid] = -1;
    }
    redI[t] = li; redT[t] = lt;
    __syncthreads();
    for (int p = t; p < P; p += 1024) {
        atomicMax(&g_winI[g_iid[p]], p);
        atomicMax(&g_winT[g_tid2[p]], p);
    }
    __syncthreads();
    for (int o = 512; o > 0; o >>= 1) {
        if (t < o) { redI[t] += redI[t + o]; redT[t] += redT[t + o]; }
        __syncthreads();
    }
    for (int p = t; p < P; p += 1024) {
        int iid = g_iid[p], tid = g_tid2[p];
        if (g_winI[iid] == p) outSI[iid] = g_sIv[p];
        if (g_winT[tid] == p) outST[tid] = g_sTv[p];
    }

    if (t == 0) {
        float contrastive = redI[0] / (float)P + redT[0] / (float)P;
        float u_sum = 0.f;
        for (int c = 0; c < C; c++) if (g_cnt[c] > 0) u_sum += u_in[c];
        float clsum = 0.f;
        int npres = 0;
        for (int c = 0; c < C; c++) {
            int cnt = g_cnt[c];
            bool present = (cnt > 0);
            float safe = (float)((cnt > 1) ? cnt : 1);
            float mean = g_ce_sum[c] / safe;
            float meanLast = g_last_sum[c] / safe;
            float cv = mean - meanLast;
            float u_upd = (u_sum == 0.0f) ? cv : (0.2f * u_in[c] + 0.8f * cv);
            float u_new = present ? u_upd : u_in[c];
            out[1 + 2 * (size_t)N + c] = u_new;
            if (present) {
                clsum += fmaxf(40.0f * u_new, 0.0f) * mean * 0.1f;
                npres++;
            }
        }
        out[0] = contrastive + clsum / (float)npres;
    }
}

// ---------------- launch ----------------
extern "C" void kernel_launch(void* const* d_in, const int* in_sizes, int n_in,
                              void* d_out, int out_size) {
    const float* img       = (const float*)d_in[0];
    const float* txt       = (const float*)d_in[1];
    const int*   image_ids = (const int*)d_in[2];
    const int*   text_ids  = (const int*)d_in[3];
    const int*   slabel    = (const int*)d_in[4];
    const int*   epoch     = (const int*)d_in[5];
    const float* img_c     = (const float*)d_in[6];
    const float* txt_c     = (const float*)d_in[7];
    const int*   labels_c  = (const int*)d_in[8];
    const float* last_l    = (const float*)d_in[9];
    const float* s_I       = (const float*)d_in[10];
    const float* s_T       = (const float*)d_in[11];
    const float* u_in      = (const float*)d_in[12];
    float* out = (float*)d_out;

    int B  = in_sizes[2];
    int D  = in_sizes[0] / B;
    int N  = in_sizes[10];
    int Bc = in_sizes[8];
    int C  = in_sizes[12];

    cudaFuncSetAttribute(mma_gemm, cudaFuncAttributeMaxDynamicSharedMemorySize, SMEM_TOTAL);

    compact_kernel<<<1, 1024>>>(slabel, B);
    diag_kernel<<<(B * 32 + 255) / 256, 256>>>(img, txt, D, B);
    prep_kernel<<<2048, 256>>>(out + 1, s_I, s_T, N);
    gather_kernel<<<B, 256>>>(img, txt, B);

    dim3 gg((B + TN - 1) / TN, (B + TM - 1) / TM, 2);
    mma_gemm<<<gg, 256, SMEM_TOTAL>>>(B);

    ce_kernel<<<(Bc * 32 + 255) / 256, 256>>>(img_c, txt_c, labels_c, last_l, Bc, D, C);

    finalize_kernel<<<1, 1024>>>(image_ids, text_ids, s_I, s_T, u_in, epoch,
                                 out, N, C, B);
}

// round 6
// speedup vs baseline: 1.7659x; 1.7659x over previous
#include <cuda_runtime.h>
#include <cuda_fp16.h>
#include <math.h>
#include <stdint.h>

// ---------------- constants / scratch ----------------
#define MAXB    8192
#define MAXC    8
#define DDIM    512
#define KD      512           // fp16 GEMM K (no split)
// log2(e)/TEMP, TEMP=0.07
#define CEXP    20.60992915555662f
// np.finfo(float32).eps
#define EPSF    1.1920928955078125e-07f

// GEMM tiling: block 128x128, 8 warps (4M x 2N), warp tile 32x64
#define TM      128
#define TN      128
#define KC      64            // fp16 per K-chunk (128 bytes per row)
#define NCHUNK  (KD / KC)     // 8
#define NSTAGE  3
#define A_BYTES (TM * 128)    // 16384
#define B_BYTES (TN * 128)    // 16384
#define STAGE_BYTES (A_BYTES + B_BYTES)       // 32768
#define SMEM_TOTAL  (NSTAGE * STAGE_BYTES)    // 98304

__device__ int   g_posIdx[MAXB];
__device__ int   g_negIdx[MAXB];
__device__ int   g_counts[1];
__device__ float g_diag[MAXB];
__device__ float g_diagP[MAXB];
__device__ float g_S1i[MAXB], g_S2i[MAXB], g_S1t[MAXB], g_S2t[MAXB];
__device__ float g_ce_sum[MAXC], g_last_sum[MAXC];
__device__ int   g_cnt[MAXC];
__device__ int   g_winI[1048576], g_winT[1048576];
__device__ float g_sIv[MAXB], g_sTv[MAXB];
__device__ int   g_iid[MAXB], g_tid2[MAXB];

// fp16 gathered matrices (pos rows / neg rows), row stride KD
__device__ __align__(16) __half g_imgP[(size_t)MAXB * KD];
__device__ __align__(16) __half g_txtP[(size_t)MAXB * KD];
__device__ __align__(16) __half g_imgN[(size_t)MAXB * KD];
__device__ __align__(16) __half g_txtN[(size_t)MAXB * KD];

// ---------------- PTX helpers (baseline ISA only: sm_80+) ----------------
__device__ __forceinline__ uint32_t smem_to_u32(const void* p) {
    uint32_t a;
    asm("{ .reg .u64 t; cvta.to.shared.u64 t, %1; cvt.u32.u64 %0, t; }" : "=r"(a) : "l"(p));
    return a;
}
#define CP_ASYNC16(sm, g) \
    asm volatile("cp.async.cg.shared.global [%0], [%1], 16;" :: "r"(sm), "l"(g))
#define CP_COMMIT() asm volatile("cp.async.commit_group;" ::: "memory")
#define CP_WAIT1()  asm volatile("cp.async.wait_group 1;"  ::: "memory")

__device__ __forceinline__ void ldsm_x4(uint32_t& r0, uint32_t& r1, uint32_t& r2,
                                        uint32_t& r3, uint32_t addr) {
    asm volatile("ldmatrix.sync.aligned.m8n8.x4.shared.b16 {%0,%1,%2,%3}, [%4];"
                 : "=r"(r0), "=r"(r1), "=r"(r2), "=r"(r3) : "r"(addr));
}
__device__ __forceinline__ void mma16816(float& c0, float& c1, float& c2, float& c3,
                                         uint32_t a0, uint32_t a1, uint32_t a2, uint32_t a3,
                                         uint32_t b0, uint32_t b1) {
    asm volatile(
        "mma.sync.aligned.m16n8k16.row.col.f32.f16.f16.f32 "
        "{%0,%1,%2,%3}, {%4,%5,%6,%7}, {%8,%9}, {%0,%1,%2,%3};"
        : "+f"(c0), "+f"(c1), "+f"(c2), "+f"(c3)
        : "r"(a0), "r"(a1), "r"(a2), "r"(a3), "r"(b0), "r"(b1));
}
__device__ __forceinline__ uint32_t sw128(uint32_t off) { return off ^ ((off >> 3) & 0x70); }

// ---------------- stable pos/neg compaction (1 block) ----------------
__global__ void compact_kernel(const int* __restrict__ slabel, int B) {
    __shared__ int scan[1024];
    int t   = threadIdx.x;
    int ipt = (B + 1023) >> 10;
    int base = t * ipt;
    int cnt = 0;
    for (int i = 0; i < ipt; i++) {
        int gi = base + i;
        if (gi < B && slabel[gi] == 1) cnt++;
    }
    scan[t] = cnt;
    __syncthreads();
    for (int off = 1; off < 1024; off <<= 1) {
        int v = (t >= off) ? scan[t - off] : 0;
        __syncthreads();
        scan[t] += v;
        __syncthreads();
    }
    int pr = scan[t] - cnt;
    for (int i = 0; i < ipt; i++) {
        int gi = base + i;
        if (gi >= B) break;
        if (slabel[gi] == 1) { g_posIdx[pr] = gi; pr++; }
        else                 { g_negIdx[gi - pr] = gi; }
    }
    if (t == 1023) g_counts[0] = scan[1023];
}

// ---------------- diag[i] = img[i] . txt[i] ----------------
__global__ void diag_kernel(const float* __restrict__ img,
                            const float* __restrict__ txt, int D, int B) {
    int gw   = (blockIdx.x * blockDim.x + threadIdx.x) >> 5;
    int lane = threadIdx.x & 31;
    if (gw >= B) return;
    const float4* a = (const float4*)(img + (size_t)gw * D);
    const float4* b = (const float4*)(txt + (size_t)gw * D);
    float s = 0.f;
    int n4 = D >> 2;
    for (int k = lane; k < n4; k += 32) {
        float4 x = a[k], y = b[k];
        s += x.x * y.x + x.y * y.y + x.z * y.z + x.w * y.w;
    }
    #pragma unroll
    for (int o = 16; o > 0; o >>= 1) s += __shfl_down_sync(0xffffffffu, s, o);
    if (lane == 0) g_diag[gw] = s;
}

// ---------------- copy persistent buffers into out + zero accumulators ----------------
__global__ void prep_kernel(float* __restrict__ dst, const float* __restrict__ sI,
                            const float* __restrict__ sT, int N) {
    int id  = blockIdx.x * blockDim.x + threadIdx.x;
    int str = gridDim.x * blockDim.x;
    for (int i = id; i < MAXB; i += str) {
        g_S1i[i] = 0.f; g_S2i[i] = 0.f; g_S1t[i] = 0.f; g_S2t[i] = 0.f;
    }
    if (id < MAXC) { g_ce_sum[id] = 0.f; g_last_sum[id] = 0.f; g_cnt[id] = 0; }
    int tot4 = (2 * N) >> 2;
    for (int i = id; i < tot4; i += str) {
        int base = i * 4;
        float4 v;
        if (base + 3 < N) {
            v = *(const float4*)(sI + base);
        } else if (base >= N) {
            v = *(const float4*)(sT + (base - N));
        } else {
            v.x = (base     < N) ? sI[base]     : sT[base - N];
            v.y = (base + 1 < N) ? sI[base + 1] : sT[base + 1 - N];
            v.z = (base + 2 < N) ? sI[base + 2] : sT[base + 2 - N];
            v.w = (base + 3 < N) ? sI[base + 3] : sT[base + 3 - N];
        }
        dst[base] = v.x; dst[base + 1] = v.y; dst[base + 2] = v.z; dst[base + 3] = v.w;
    }
    for (int i = tot4 * 4 + id; i < 2 * N; i += str)
        dst[i] = (i < N) ? sI[i] : sT[i - N];
}

// ---------------- gather + fp16 convert ----------------
// block s < P: pos slot (A rows); else neg slot (B rows). Row stride KD, fp16.
__global__ void gather_kernel(const float* __restrict__ img,
                              const float* __restrict__ txt, int B) {
    int P = g_counts[0];
    int s = blockIdx.x;
    if (s >= B) return;
    int t = threadIdx.x;          // 256 threads, 2 elems each
    bool isPos = (s < P);
    int src;
    __half *dI, *dT;
    if (isPos) {
        src = g_posIdx[s];
        dI = g_imgP + (size_t)s * KD; dT = g_txtP + (size_t)s * KD;
        if (t == 0) g_diagP[s] = g_diag[src];
    } else {
        int n = s - P;
        src = g_negIdx[n];
        dI = g_imgN + (size_t)n * KD; dT = g_txtN + (size_t)n * KD;
    }
    int k2 = 2 * t;               // D = 512, 256 threads
    {
        float2 v = *(const float2*)(img + (size_t)src * DDIM + k2);
        *(__half2*)(dI + k2) = __floats2half2_rn(v.x, v.y);
    }
    {
        float2 v = *(const float2*)(txt + (size_t)src * DDIM + k2);
        *(__half2*)(dT + k2) = __floats2half2_rn(v.x, v.y);
    }
}

// ---------------- mma.sync fp16 GEMM + fused exp epilogue ----------------
// z==0: A=g_imgP, B=g_txtN -> S1i/S2i ; z==1: A=g_txtP, B=g_imgN -> S1t/S2t
// Block 128x128, 8 warps (4M x 2N), warp tile 32x64, 3-stage cp.async, 2 CTA/SM.
__global__ void __launch_bounds__(256, 2)
mma_gemm(int Btot) {
    int M     = g_counts[0];
    int Ncols = Btot - M;
    int br = blockIdx.y * TM;
    int bc = blockIdx.x * TN;
    if (br >= M || bc >= Ncols) return;
    int which = blockIdx.z;

    extern __shared__ char smem[];
    uint32_t smem_base = smem_to_u32(smem);
    int tid  = threadIdx.x;
    int wid  = tid >> 5;
    int lane = tid & 31;
    int warp_m = wid & 3;     // 0..3
    int warp_n = wid >> 2;    // 0..1

    const __half* Abuf = which ? g_txtP : g_imgP;
    const __half* Bbuf = which ? g_imgN : g_txtN;

    // cp.async plan: unit u = tid + j*256 (j=0..3): row = (tid>>3)+32j, kb = (tid&7)*16
    int ldRow = tid >> 3;
    int ldKb  = (tid & 7) * 16;
    const char* gA0 = (const char*)Abuf + ((size_t)(br + ldRow) * KD) * 2 + ldKb;
    const char* gB0 = (const char*)Bbuf + ((size_t)(bc + ldRow) * KD) * 2 + ldKb;
    uint32_t ldOff = sw128((uint32_t)ldRow * 128 + (uint32_t)ldKb);
    const size_t rowStr = (size_t)32 * KD * 2;   // 32 rows per j step

    // ldmatrix address components
    uint32_t aRow = (uint32_t)(warp_m * 32 + (lane & 15));
    uint32_t aKb  = (uint32_t)((lane >> 4) * 16);
    uint32_t bRow = (uint32_t)(warp_n * 64 + (lane & 7) + ((lane >> 4) << 3));
    uint32_t bKb  = (uint32_t)(((lane >> 3) & 1) * 16);

    float acc[2][8][4];
    #pragma unroll
    for (int i = 0; i < 2; i++)
        #pragma unroll
        for (int j = 0; j < 8; j++)
            #pragma unroll
            for (int q = 0; q < 4; q++) acc[i][j][q] = 0.f;

    // prefetch chunks 0,1 (stages 0,1)
    #pragma unroll
    for (int pc = 0; pc < 2; pc++) {
        uint32_t sA = smem_base + pc * STAGE_BYTES;
        uint32_t sB = sA + A_BYTES;
        const char* pA = gA0 + (size_t)pc * 128;
        const char* pB = gB0 + (size_t)pc * 128;
        #pragma unroll
        for (int j = 0; j < 4; j++) {
            CP_ASYNC16(sA + ldOff + j * 4096, pA + j * rowStr);
            CP_ASYNC16(sB + ldOff + j * 4096, pB + j * rowStr);
        }
        CP_COMMIT();
    }

    int stC = 0;   // stage of chunk c
    for (int c = 0; c < NCHUNK; c++) {
        CP_WAIT1();
        __syncthreads();
        if (c + 2 < NCHUNK) {
            int sp = stC + 2; if (sp >= NSTAGE) sp -= NSTAGE;
            uint32_t sA = smem_base + sp * STAGE_BYTES;
            uint32_t sB = sA + A_BYTES;
            const char* pA = gA0 + (size_t)(c + 2) * 128;
            const char* pB = gB0 + (size_t)(c + 2) * 128;
            #pragma unroll
            for (int j = 0; j < 4; j++) {
                CP_ASYNC16(sA + ldOff + j * 4096, pA + j * rowStr);
                CP_ASYNC16(sB + ldOff + j * 4096, pB + j * rowStr);
            }
        }
        CP_COMMIT();

        uint32_t sA = smem_base + stC * STAGE_BYTES;
        uint32_t sB = sA + A_BYTES;
        #pragma unroll
        for (int k16 = 0; k16 < 4; k16++) {
            uint32_t kbase = (uint32_t)(k16 * 32);
            uint32_t a[2][4];
            #pragma unroll
            for (int mt = 0; mt < 2; mt++) {
                uint32_t addr = sA + sw128((aRow + mt * 16) * 128 + kbase + aKb);
                ldsm_x4(a[mt][0], a[mt][1], a[mt][2], a[mt][3], addr);
            }
            uint32_t b[8][2];
            #pragma unroll
            for (int np = 0; np < 4; np++) {
                uint32_t addr = sB + sw128((bRow + np * 16) * 128 + kbase + bKb);
                uint32_t r0, r1, r2, r3;
                ldsm_x4(r0, r1, r2, r3, addr);
                b[np * 2][0] = r0; b[np * 2][1] = r1;
                b[np * 2 + 1][0] = r2; b[np * 2 + 1][1] = r3;
            }
            #pragma unroll
            for (int mt = 0; mt < 2; mt++)
                #pragma unroll
                for (int nt = 0; nt < 8; nt++)
                    mma16816(acc[mt][nt][0], acc[mt][nt][1], acc[mt][nt][2], acc[mt][nt][3],
                             a[mt][0], a[mt][1], a[mt][2], a[mt][3],
                             b[nt][0], b[nt][1]);
        }
        if (++stC >= NSTAGE) stC = 0;
    }

    // fused epilogue: d = acc - diag; e = exp(d/T); S1 += e; S2 += e*d
    float* S1 = which ? g_S1t : g_S1i;
    float* S2 = which ? g_S2t : g_S2i;
    int quad = lane & 3;
    #pragma unroll
    for (int mt = 0; mt < 2; mt++) {
        #pragma unroll
        for (int half = 0; half < 2; half++) {
            int rl = warp_m * 32 + mt * 16 + (lane >> 2) + half * 8;
            int rg = br + rl;
            float dg = (rg < M) ? g_diagP[rg] : 0.f;
            float s1 = 0.f, s2 = 0.f;
            #pragma unroll
            for (int nt = 0; nt < 8; nt++) {
                #pragma unroll
                for (int q = 0; q < 2; q++) {
                    int cg = bc + warp_n * 64 + nt * 8 + quad * 2 + q;
                    if (cg < Ncols) {
                        float d = acc[mt][nt][half * 2 + q] - dg;
                        float e = exp2f(d * CEXP);
                        s1 += e;
                        s2 += e * d;
                    }
                }
            }
            s1 += __shfl_down_sync(0xffffffffu, s1, 1, 4);
            s1 += __shfl_down_sync(0xffffffffu, s1, 2, 4);
            s2 += __shfl_down_sync(0xffffffffu, s2, 1, 4);
            s2 += __shfl_down_sync(0xffffffffu, s2, 2, 4);
            if (quad == 0 && rg < M) {
                atomicAdd(&S1[rg], s1);
                atomicAdd(&S2[rg], s2);
            }
        }
    }
}

// ---------------- CE penalty branch ----------------
__global__ void ce_kernel(const float* __restrict__ imgc, const float* __restrict__ txtc,
                          const int* __restrict__ labels, const float* __restrict__ lastl,
                          int Bc, int D, int C) {
    __shared__ float sw[2560];
    int t = threadIdx.x;
    for (int i = t; i < C * D; i += blockDim.x) sw[i] = txtc[i];
    __syncthreads();

    int gw   = (blockIdx.x * blockDim.x + t) >> 5;
    int lane = t & 31;
    if (gw >= Bc) return;

    const float4* a = (const float4*)(imgc + (size_t)gw * D);
    float acc[5] = {0.f, 0.f, 0.f, 0.f, 0.f};
    int n4 = D >> 2;
    for (int k = lane; k < n4; k += 32) {
        float4 x = a[k];
        #pragma unroll
        for (int c = 0; c < 5; c++) {
            float4 w = *(const float4*)&sw[c * D + k * 4];
            acc[c] += x.x * w.x + x.y * w.y + x.z * w.z + x.w * w.w;
        }
    }
    #pragma unroll
    for (int c = 0; c < 5; c++) {
        #pragma unroll
        for (int o = 16; o > 0; o >>= 1)
            acc[c] += __shfl_down_sync(0xffffffffu, acc[c], o);
    }
    if (lane == 0) {
        float logits[5], m = -1e30f;
        #pragma unroll
        for (int c = 0; c < 5; c++) { logits[c] = acc[c] * 10.0f; m = fmaxf(m, logits[c]); }
        float se = 0.f;
        #pragma unroll
        for (int c = 0; c < 5; c++) se += expf(logits[c] - m);
        float lse = m + logf(se);
        int lb = labels[gw];
        float ce = lse - logits[lb];
        atomicAdd(&g_ce_sum[lb], ce);
        atomicAdd(&g_cnt[lb], 1);
        atomicAdd(&g_last_sum[lb], lastl[gw]);
    }
}

// ---------------- finalize (single block) ----------------
__global__ void finalize_kernel(const int* __restrict__ image_ids,
                                const int* __restrict__ text_ids,
                                const float* __restrict__ s_I,
                                const float* __restrict__ s_T,
                                const float* __restrict__ u_in,
                                const int* __restrict__ epoch_ptr,
                                float* __restrict__ out, int N, int C, int B) {
    __shared__ float redI[1024], redT[1024];
    int t = threadIdx.x;
    int P = g_counts[0];
    int Nn = B - P;
    int epoch = *epoch_ptr;
    float invNn = 1.0f / (float)Nn;
    float* outSI = out + 1;
    float* outST = out + 1 + N;

    float li = 0.f, lt = 0.f;
    for (int p = t; p < P; p += 1024) {
        int row = g_posIdx[p];
        float gI = g_S1i[p] * invNn;
        float gT = g_S1t[p] * invNn;
        int iid = image_ids[row];
        int tid = text_ids[row];
        float sIv, sTv;
        if (epoch == 0) { sIv = gI; sTv = gT; }
        else {
            sIv = 0.2f * s_I[iid] + 0.8f * gI;
            sTv = 0.2f * s_T[tid] + 0.8f * gT;
        }
        li += (g_S2i[p] * invNn) / (sIv + EPSF);
        lt += (g_S2t[p] * invNn) / (sTv + EPSF);
        g_sIv[p] = sIv; g_sTv[p] = sTv;
        g_iid[p] = iid; g_tid2[p] = tid;
        g_winI[iid] = -1;
        g_winT[tid] = -1;
    }
    redI[t] = li; redT[t] = lt;
    __syncthreads();
    for (int p = t; p < P; p += 1024) {
        atomicMax(&g_winI[g_iid[p]], p);
        atomicMax(&g_winT[g_tid2[p]], p);
    }
    __syncthreads();
    for (int o = 512; o > 0; o >>= 1) {
        if (t < o) { redI[t] += redI[t + o]; redT[t] += redT[t + o]; }
        __syncthreads();
    }
    for (int p = t; p < P; p += 1024) {
        int iid = g_iid[p], tid = g_tid2[p];
        if (g_winI[iid] == p) outSI[iid] = g_sIv[p];
        if (g_winT[tid] == p) outST[tid] = g_sTv[p];
    }

    if (t == 0) {
        float contrastive = redI[0] / (float)P + redT[0] / (float)P;
        float u_sum = 0.f;
        for (int c = 0; c < C; c++) if (g_cnt[c] > 0) u_sum += u_in[c];
        float clsum = 0.f;
        int npres = 0;
        for (int c = 0; c < C; c++) {
            int cnt = g_cnt[c];
            bool present = (cnt > 0);
            float safe = (float)((cnt > 1) ? cnt : 1);
            float mean = g_ce_sum[c] / safe;
            float meanLast = g_last_sum[c] / safe;
            float cv = mean - meanLast;
            float u_upd = (u_sum == 0.0f) ? cv : (0.2f * u_in[c] + 0.8f * cv);
            float u_new = present ? u_upd : u_in[c];
            out[1 + 2 * (size_t)N + c] = u_new;
            if (present) {
                clsum += fmaxf(40.0f * u_new, 0.0f) * mean * 0.1f;
                npres++;
            }
        }
        out[0] = contrastive + clsum / (float)npres;
    }
}

// ---------------- launch ----------------
extern "C" void kernel_launch(void* const* d_in, const int* in_sizes, int n_in,
                              void* d_out, int out_size) {
    const float* img       = (const float*)d_in[0];
    const float* txt       = (const float*)d_in[1];
    const int*   image_ids = (const int*)d_in[2];
    const int*   text_ids  = (const int*)d_in[3];
    const int*   slabel    = (const int*)d_in[4];
    const int*   epoch     = (const int*)d_in[5];
    const float* img_c     = (const float*)d_in[6];
    const float* txt_c     = (const float*)d_in[7];
    const int*   labels_c  = (const int*)d_in[8];
    const float* last_l    = (const float*)d_in[9];
    const float* s_I       = (const float*)d_in[10];
    const float* s_T       = (const float*)d_in[11];
    const float* u_in      = (const float*)d_in[12];
    float* out = (float*)d_out;

    int B  = in_sizes[2];
    int D  = in_sizes[0] / B;
    int N  = in_sizes[10];
    int Bc = in_sizes[8];
    int C  = in_sizes[12];

    cudaFuncSetAttribute(mma_gemm, cudaFuncAttributeMaxDynamicSharedMemorySize, SMEM_TOTAL);

    compact_kernel<<<1, 1024>>>(slabel, B);
    diag_kernel<<<(B * 32 + 255) / 256, 256>>>(img, txt, D, B);
    prep_kernel<<<2048, 256>>>(out + 1, s_I, s_T, N);
    gather_kernel<<<B, 256>>>(img, txt, B);

    dim3 gg((B + TN - 1) / TN, (B + TM - 1) / TM, 2);
    mma_gemm<<<gg, 256, SMEM_TOTAL>>>(B);

    ce_kernel<<<(Bc * 32 + 255) / 256, 256>>>(img_c, txt_c, labels_c, last_l, Bc, D, C);

    finalize_kernel<<<1, 1024>>>(image_ids, text_ids, s_I, s_T, u_in, epoch,
                                 out, N, C, B);
}